// round 3
// baseline (speedup 1.0000x reference)
#include <cuda_runtime.h>
#include <cuda_fp16.h>
#include <cuda_fp8.h>
#include <cstdint>
#include <cstddef>

#define M_DIM 8192
#define N_DIM 4096
#define K_DIM 4096

// ---------------- scratch (static device globals: allowed) ----------------
__device__ __half g_A[(size_t)M_DIM * K_DIM];   // fp16(e4m3(x/s)*s)
__device__ __half g_B[(size_t)N_DIM * K_DIM];   // fp16(e4m3(w)*ws)

// ---------------- helpers ----------------
__device__ __forceinline__ uint32_t smem_u32(const void* p) {
    uint32_t a;
    asm("{ .reg .u64 t; cvta.to.shared.u64 t, %1; cvt.u32.u64 %0, t; }"
        : "=r"(a) : "l"(p));
    return a;
}
__device__ __forceinline__ uint32_t swz128(uint32_t off) {
    return off ^ ((off >> 3) & 0x70u);
}
__device__ __forceinline__ void cp_async16(uint32_t s, const void* g) {
    asm volatile("cp.async.cg.shared.global [%0], [%1], 16;\n" :: "r"(s), "l"(g));
}
#define CP_COMMIT()  asm volatile("cp.async.commit_group;\n" ::: "memory")
#define CP_WAIT(N_)  asm volatile("cp.async.wait_group %0;\n" :: "n"(N_) : "memory")

__device__ __forceinline__ void ldmatrix_x4(uint32_t& r0, uint32_t& r1,
                                            uint32_t& r2, uint32_t& r3,
                                            uint32_t addr) {
    asm volatile("ldmatrix.sync.aligned.m8n8.x4.shared.b16 {%0,%1,%2,%3}, [%4];"
                 : "=r"(r0), "=r"(r1), "=r"(r2), "=r"(r3) : "r"(addr));
}

__device__ __forceinline__ void mma_16816(float* d, const uint32_t* a,
                                          const uint32_t* b) {
    asm volatile(
        "mma.sync.aligned.m16n8k16.row.col.f32.f16.f16.f32 "
        "{%0,%1,%2,%3}, {%4,%5,%6,%7}, {%8,%9}, {%0,%1,%2,%3};"
        : "+f"(d[0]), "+f"(d[1]), "+f"(d[2]), "+f"(d[3])
        : "r"(a[0]), "r"(a[1]), "r"(a[2]), "r"(a[3]), "r"(b[0]), "r"(b[1]));
}

// ---------------- e4m3 round-trip (RN-even + satfinite, matches ml_dtypes) --
__device__ __forceinline__ float fp8_roundtrip(float t) {
    __nv_fp8_storage_t q = __nv_cvt_float_to_fp8(t, __NV_SATFINITE, __NV_E4M3);
    __half_raw hr = __nv_cvt_fp8_to_halfraw(q, __NV_E4M3);
    return __half2float(*reinterpret_cast<__half*>(&hr));
}

// ---------------- kernel 1: activation blockwise quant -> fp16 -------------
__global__ void __launch_bounds__(256) quant_x_kernel(const float* __restrict__ x) {
    int gw   = (blockIdx.x * 256 + threadIdx.x) >> 5;   // global warp id
    int lane = threadIdx.x & 31;
    int row  = gw >> 5;        // Kb = 32
    int kb   = gw & 31;

    const float4 v = *reinterpret_cast<const float4*>(
        x + (size_t)row * K_DIM + kb * 128 + lane * 4);
    float a = fmaxf(fmaxf(fabsf(v.x), fabsf(v.y)), fmaxf(fabsf(v.z), fabsf(v.w)));
#pragma unroll
    for (int o = 16; o; o >>= 1) a = fmaxf(a, __shfl_xor_sync(0xffffffffu, a, o));
    float scale = __fdiv_rn(fmaxf(a, 1e-12f), 448.0f);

    float vv[4] = {v.x, v.y, v.z, v.w};
    __half h[4];
#pragma unroll
    for (int j = 0; j < 4; j++) {
        float dq = fp8_roundtrip(__fdiv_rn(vv[j], scale));
        h[j] = __float2half_rn(dq * scale);
    }
    *reinterpret_cast<uint2*>(g_A + (size_t)row * K_DIM + kb * 128 + lane * 4) =
        *reinterpret_cast<uint2*>(h);
}

// ---------------- kernel 2: weight dequant -> fp16 -------------------------
__global__ void __launch_bounds__(256) quant_w_kernel(const float* __restrict__ w,
                                                      const float* __restrict__ ws) {
    size_t i  = (size_t)blockIdx.x * 256 + threadIdx.x;  // one float4 each
    int row   = (int)(i >> 10);          // K/4 = 1024
    int c4    = (int)(i & 1023);
    float s   = ws[(row >> 7) * 32 + (c4 >> 5)];

    float4 v = reinterpret_cast<const float4*>(w)[i];
    float vv[4] = {v.x, v.y, v.z, v.w};
    __half h[4];
#pragma unroll
    for (int j = 0; j < 4; j++)
        h[j] = __float2half_rn(fp8_roundtrip(vv[j]) * s);
    *reinterpret_cast<uint2*>(g_B + (size_t)row * K_DIM + c4 * 4) =
        *reinterpret_cast<uint2*>(h);
}

// ---------------- kernel 3: GEMM out[M,N] = A[M,K] @ B[N,K]^T --------------
#define BM 128
#define BN 256
#define BK 64
#define STAGES 4
#define NSLAB (K_DIM / BK)                 // 64
#define A_STG_BYTES (BM * 128)             // 16384
#define B_STG_BYTES (BN * 128)             // 32768
#define STG_BYTES   (A_STG_BYTES + B_STG_BYTES)   // 49152
#define SMEM_DYN    (STAGES * STG_BYTES)   // 196608

// one stage: A chunks 1024 (4/thread), B chunks 2048 (8/thread), 16B each
__device__ __forceinline__ void load_slab(int tid, uint32_t sA, uint32_t sB,
                                          const __half* Ag, const __half* Bg) {
#pragma unroll
    for (int i = 0; i < 4; i++) {
        int c = tid + 256 * i;
        int r = c >> 3, seg = c & 7;
        cp_async16(sA + swz128((uint32_t)(r * 128 + seg * 16)),
                   Ag + (size_t)r * K_DIM + seg * 8);
    }
#pragma unroll
    for (int i = 0; i < 8; i++) {
        int c = tid + 256 * i;
        int r = c >> 3, seg = c & 7;
        cp_async16(sB + swz128((uint32_t)(r * 128 + seg * 16)),
                   Bg + (size_t)r * K_DIM + seg * 8);
    }
}

__global__ void __launch_bounds__(256, 1)
gemm_kernel(float* __restrict__ out) {
    extern __shared__ char dsm[];
    const uint32_t sb = smem_u32(dsm);

    int tid  = threadIdx.x;
    int wid  = tid >> 5;
    int lane = tid & 31;
    int wm   = wid & 1;        // 2 warps along M (64 rows each)
    int wn   = wid >> 1;       // 4 warps along N (64 cols each)
    int m_base = blockIdx.y * BM;
    int n_base = blockIdx.x * BN;

    const __half* Abase = g_A + (size_t)m_base * K_DIM;
    const __half* Bbase = g_B + (size_t)n_base * K_DIM;

    // prologue: stages 0..STAGES-2
#pragma unroll
    for (int p = 0; p < STAGES - 1; p++) {
        load_slab(tid, sb + p * STG_BYTES, sb + p * STG_BYTES + A_STG_BYTES,
                  Abase + p * BK, Bbase + p * BK);
        CP_COMMIT();
    }

    float acc[4][8][4];
#pragma unroll
    for (int mt = 0; mt < 4; mt++)
#pragma unroll
        for (int nt = 0; nt < 8; nt++)
#pragma unroll
            for (int j = 0; j < 4; j++) acc[mt][nt][j] = 0.0f;

    // precomputed (per-lane) pieces of ldmatrix addressing
    const uint32_t a_row = (uint32_t)(wm * 64 + (lane & 15));      // + mt*16
    const uint32_t a_ch  = (uint32_t)(lane >> 4);                  // + 2*kk
    const uint32_t b_row = (uint32_t)(wn * 64 + (lane & 7) + ((lane >> 4) << 3));
    const uint32_t b_ch  = (uint32_t)((lane >> 3) & 1);            // + 2*kk

    for (int s = 0; s < NSLAB; s++) {
        CP_WAIT(STAGES - 2);
        __syncthreads();

        // issue slab s+STAGES-1
        {
            int ns = s + STAGES - 1;
            if (ns < NSLAB) {
                uint32_t stg = sb + (uint32_t)(ns % STAGES) * STG_BYTES;
                load_slab(tid, stg, stg + A_STG_BYTES,
                          Abase + ns * BK, Bbase + ns * BK);
            }
            CP_COMMIT();   // empty group ok — keeps group accounting aligned
        }

        const uint32_t stg = sb + (uint32_t)(s % STAGES) * STG_BYTES;
        const uint32_t sA = stg, sBB = stg + A_STG_BYTES;

#pragma unroll
        for (int kk = 0; kk < 4; kk++) {
            uint32_t af[4][4];
#pragma unroll
            for (int mt = 0; mt < 4; mt++) {
                uint32_t off = (a_row + mt * 16) * 128 + (a_ch + 2 * kk) * 16;
                ldmatrix_x4(af[mt][0], af[mt][1], af[mt][2], af[mt][3],
                            sA + swz128(off));
            }
            uint32_t bf[8][2];
#pragma unroll
            for (int nt2 = 0; nt2 < 4; nt2++) {
                uint32_t off = (b_row + nt2 * 16) * 128 + (b_ch + 2 * kk) * 16;
                uint32_t r0, r1, r2, r3;
                ldmatrix_x4(r0, r1, r2, r3, sBB + swz128(off));
                bf[nt2 * 2][0] = r0; bf[nt2 * 2][1] = r1;
                bf[nt2 * 2 + 1][0] = r2; bf[nt2 * 2 + 1][1] = r3;
            }
#pragma unroll
            for (int mt = 0; mt < 4; mt++)
#pragma unroll
                for (int nt = 0; nt < 8; nt++)
                    mma_16816(acc[mt][nt], af[mt], bf[nt]);
        }
    }

    // ---------------- epilogue: direct coalesced stores --------------------
    int mrow0 = m_base + wm * 64 + (lane >> 2);
    int ncol0 = n_base + wn * 64 + (lane & 3) * 2;
#pragma unroll
    for (int mt = 0; mt < 4; mt++) {
#pragma unroll
        for (int nt = 0; nt < 8; nt++) {
            int m0 = mrow0 + mt * 16;
            int n0 = ncol0 + nt * 8;
            float2 v0 = {acc[mt][nt][0], acc[mt][nt][1]};
            float2 v1 = {acc[mt][nt][2], acc[mt][nt][3]};
            *reinterpret_cast<float2*>(out + (size_t)m0 * N_DIM + n0) = v0;
            *reinterpret_cast<float2*>(out + (size_t)(m0 + 8) * N_DIM + n0) = v1;
        }
    }
}

// ---------------- launch ----------------------------------------------------
extern "C" void kernel_launch(void* const* d_in, const int* in_sizes, int n_in,
                              void* d_out, int out_size) {
    const float* x  = (const float*)d_in[0];
    const float* w  = (const float*)d_in[1];
    const float* ws = (const float*)d_in[2];
    float* out = (float*)d_out;

    cudaFuncSetAttribute(gemm_kernel, cudaFuncAttributeMaxDynamicSharedMemorySize,
                         SMEM_DYN);

    quant_x_kernel<<<(M_DIM * 32) / 8, 256>>>(x);
    quant_w_kernel<<<(N_DIM * (K_DIM / 4)) / 256, 256>>>(w, ws);
    gemm_kernel<<<dim3(N_DIM / BN, M_DIM / BM), 256, SMEM_DYN>>>(out);
}